// round 5
// baseline (speedup 1.0000x reference)
#include <cuda_runtime.h>
#include <cuda_fp16.h>
#include <cstdint>
#include <math.h>

// ---------------- scratch (no allocations allowed) ----------------
#define N_LEAVES_MAX 100000
#define MAXB 256
#define GRID_B 128

__device__ __align__(16) __half g_dleaf[N_LEAVES_MAX + 128];
__device__ int    g_maxint;          // max d as ordered int (positive floats)
__device__ float4 g_part[MAXB];      // (sum_exp, sum_sims_exp, sum_sims, -)

// ---------------- mbarrier / bulk-copy helpers ----------------
__device__ __forceinline__ void mbar_init(unsigned int mbar, unsigned int cnt) {
    asm volatile("mbarrier.init.shared.b64 [%0], %1;" :: "r"(mbar), "r"(cnt) : "memory");
}
__device__ __forceinline__ void mbar_expect_tx(unsigned int mbar, unsigned int bytes) {
    asm volatile("mbarrier.arrive.expect_tx.shared.b64 _, [%0], %1;"
                 :: "r"(mbar), "r"(bytes) : "memory");
}
__device__ __forceinline__ void mbar_wait(unsigned int mbar, unsigned int phase) {
    asm volatile(
        "{\n\t"
        ".reg .pred P1;\n\t"
        "WAIT_LOOP_%=:\n\t"
        "mbarrier.try_wait.parity.acquire.cta.shared::cta.b64 P1, [%0], %1, 0x989680;\n\t"
        "@P1 bra.uni WAIT_DONE_%=;\n\t"
        "bra.uni WAIT_LOOP_%=;\n\t"
        "WAIT_DONE_%=:\n\t"
        "}"
        :: "r"(mbar), "r"(phase) : "memory");
}
__device__ __forceinline__ void bulk_g2s(unsigned int dst, const void* src,
                                         unsigned int bytes, unsigned int mbar) {
    asm volatile(
        "cp.async.bulk.shared::cluster.global.mbarrier::complete_tx::bytes [%0], [%1], %2, [%3];"
        :: "r"(dst), "l"(src), "r"(bytes), "r"(mbar) : "memory");
}

#define TILE_A 128
#define ROWF   132                            // padded floats/row (528 B)
#define STAGE_BYTES (TILE_A * ROWF * 4)       // 67584

// ---------------- Kernel A: persistent double-buffered leaf distances ----------------
__global__ __launch_bounds__(128) void leaf_dist_kernel(
        const int* __restrict__ lca,
        const float* __restrict__ emb,
        const float* __restrict__ leaves,
        const float* __restrict__ scale,
        int n_leaves)
{
    extern __shared__ float sm[];        // [2][TILE_A*ROWF]
    __shared__ __align__(16) float s_e[128];
    __shared__ float s_red[128];
    __shared__ float s_nx, s_inv;
    __shared__ __align__(8) unsigned long long s_mbar[2];

    const int t       = threadIdx.x;
    const int bx      = blockIdx.x;
    const int grid    = gridDim.x;
    const int n_tiles = (n_leaves + TILE_A - 1) / TILE_A;
    const unsigned int sbase = (unsigned int)__cvta_generic_to_shared(sm);
    const unsigned int mb0   = (unsigned int)__cvta_generic_to_shared(&s_mbar[0]);

    const int my_n = (bx < n_tiles) ? (n_tiles - bx + grid - 1) / grid : 0;

    if (t == 0) { mbar_init(mb0, 1); mbar_init(mb0 + 8, 1); }
    __syncthreads();

    // ---- prologue: post expects, then issue row bulk-copies for stages 0,1 ----
    if (t == 0) {
        #pragma unroll
        for (int p = 0; p < 2; p++) {
            int tile = bx + p * grid;
            if (tile < n_tiles) {
                int valid = min(TILE_A, n_leaves - tile * TILE_A);
                mbar_expect_tx(mb0 + p * 8, valid * 512u);
            }
        }
    }
    __syncthreads();   // expects visible before any complete_tx can land
    #pragma unroll
    for (int p = 0; p < 2; p++) {
        int tile = bx + p * grid;
        if (tile < n_tiles) {
            int leaf0 = tile * TILE_A;
            int valid = min(TILE_A, n_leaves - leaf0);
            if (t < valid)
                bulk_g2s(sbase + p * STAGE_BYTES + t * (ROWF * 4),
                         leaves + (size_t)(leaf0 + t) * 128, 512u, mb0 + p * 8);
        }
    }

    // ---- build e1 while prologue loads fly ----
    const float* erow = emb + (long long)lca[0] * 128;
    float w = erow[t];
    s_red[t] = w * w;
    __syncthreads();
    for (int off = 64; off > 0; off >>= 1) {
        if (t < off) s_red[t] += s_red[t + off];
        __syncthreads();
    }
    if (t == 0) {
        float norm2  = s_red[0];
        float s      = fminf(fmaxf(scale[0], 0.01f), 1.0f - 0.001f);
        float factor = s / fmaxf(sqrtf(norm2), 1e-12f);
        float nx     = factor * factor * norm2;
        s_nx  = nx;
        s_inv = 1.0f / (1.0f - nx);
        s_red[0] = factor;
    }
    __syncthreads();
    s_e[t] = w * s_red[0];
    __syncthreads();                       // s_e/s_nx/s_inv visible

    float dmax = 0.0f;
    const float4* er = reinterpret_cast<const float4*>(s_e);

    #pragma unroll 1
    for (int i = 0; i < my_n; i++) {
        const int st = i & 1;
        mbar_wait(mb0 + st * 8, (i >> 1) & 1);

        const int tile  = bx + i * grid;
        const int leaf0 = tile * TILE_A;
        const int valid = min(TILE_A, n_leaves - leaf0);
        const float* stg = sm + st * (TILE_A * ROWF);

        if (t < valid) {
            const float4* yr = reinterpret_cast<const float4*>(stg + t * ROWF);
            float dot = 0.0f, ny = 0.0f;
            #pragma unroll
            for (int k = 0; k < 32; k++) {
                float4 y = yr[k];
                float4 e = er[k];      // broadcast
                dot = fmaf(e.x, y.x, fmaf(e.y, y.y, fmaf(e.z, y.z, fmaf(e.w, y.w, dot))));
                ny  = fmaf(y.x, y.x, fmaf(y.y, y.y, fmaf(y.z, y.z, fmaf(y.w, y.w, ny))));
            }
            float sq  = s_nx - 2.0f * dot + ny;
            float arg = 1.0f + 2.0f * sq * s_inv / (1.0f - ny);
            arg = fmaxf(arg, 1.0f + 1e-7f);
            float d = acoshf(arg);
            g_dleaf[leaf0 + t] = __float2half(d);
            dmax = fmaxf(dmax, d);
        }

        // ---- refill this stage with tile i+2 ----
        const int tile2 = bx + (i + 2) * grid;
        int v2 = 0, l2 = 0;
        if (tile2 < n_tiles) {
            l2 = tile2 * TILE_A;
            v2 = min(TILE_A, n_leaves - l2);
            if (t == 0) mbar_expect_tx(mb0 + st * 8, v2 * 512u);
        }
        __syncthreads();   // stage consumed by all + expect visible
        if (tile2 < n_tiles && t < v2)
            bulk_g2s(sbase + st * STAGE_BYTES + t * (ROWF * 4),
                     leaves + (size_t)(l2 + t) * 128, 512u, mb0 + st * 8);
    }

    // ---- block max -> global atomicMax (deterministic) ----
    s_red[t] = dmax;
    __syncthreads();
    for (int off = 64; off > 0; off >>= 1) {
        if (t < off) s_red[t] = fmaxf(s_red[t], s_red[t + off]);
        __syncthreads();
    }
    if (t == 0) atomicMax(&g_maxint, __float_as_int(s_red[0]));
}

// ---------------- Kernel B: branchless softmax partial sums ----------------
__global__ __launch_bounds__(1024) void pair_reduce_kernel(
        const int* __restrict__ l_idx,
        const int* __restrict__ r_idx,
        const float* __restrict__ sims,
        int n_pairs, int n_leaves)
{
    extern __shared__ __half s_tab[];
    __shared__ float r_se[1024], r_ss[1024], r_su[1024];
    __shared__ __align__(8) unsigned long long s_mbar;

    const int t = threadIdx.x;
    const unsigned int sb  = (unsigned int)__cvta_generic_to_shared(s_tab);
    const unsigned int mbr = (unsigned int)__cvta_generic_to_shared(&s_mbar);

    const unsigned int totr  = ((unsigned int)n_leaves * 2u + 127u) & ~127u;
    const unsigned int chunk = totr / 8u;

    if (t == 0) { mbar_init(mbr, 1); mbar_expect_tx(mbr, totr); }
    __syncthreads();
    if (t < 8)
        bulk_g2s(sb + t * chunk, reinterpret_cast<const char*>(g_dleaf) + t * chunk,
                 chunk, mbr);

    const float M = 40.0f * __int_as_float(g_maxint);

    mbar_wait(mbr, 0);       // every thread: acquire -> safe LDS reads

    float se = 0.0f, ss = 0.0f, su = 0.0f;

    const int n4 = n_pairs >> 2;
    const int4*   l4 = reinterpret_cast<const int4*>(l_idx);
    const int4*   r4 = reinterpret_cast<const int4*>(r_idx);
    const float4* s4 = reinterpret_cast<const float4*>(sims);
    const int stride = gridDim.x * blockDim.x;

    #pragma unroll 2
    for (int i = blockIdx.x * blockDim.x + t; i < n4; i += stride) {
        int4   li = l4[i];
        int4   ri = r4[i];
        float4 si = s4[i];
        float e0 = __expf(fmaf(20.0f, __half2float(s_tab[li.x]) + __half2float(s_tab[ri.x]), -M));
        float e1 = __expf(fmaf(20.0f, __half2float(s_tab[li.y]) + __half2float(s_tab[ri.y]), -M));
        float e2 = __expf(fmaf(20.0f, __half2float(s_tab[li.z]) + __half2float(s_tab[ri.z]), -M));
        float e3 = __expf(fmaf(20.0f, __half2float(s_tab[li.w]) + __half2float(s_tab[ri.w]), -M));
        se += (e0 + e1) + (e2 + e3);
        ss  = fmaf(si.x, e0, fmaf(si.y, e1, fmaf(si.z, e2, fmaf(si.w, e3, ss))));
        su += (si.x + si.y) + (si.z + si.w);
    }
    // scalar tail
    if (blockIdx.x == 0) {
        for (int i = n4 * 4 + t; i < n_pairs; i += blockDim.x) {
            float e = __expf(fmaf(20.0f,
                        __half2float(s_tab[l_idx[i]]) + __half2float(s_tab[r_idx[i]]), -M));
            float si = sims[i];
            se += e; ss = fmaf(si, e, ss); su += si;
        }
    }

    r_se[t] = se; r_ss[t] = ss; r_su[t] = su;
    __syncthreads();
    for (int off = 512; off > 0; off >>= 1) {
        if (t < off) {
            r_se[t] += r_se[t + off];
            r_ss[t] += r_ss[t + off];
            r_su[t] += r_su[t + off];
        }
        __syncthreads();
    }
    if (t == 0) g_part[blockIdx.x] = make_float4(r_se[0], r_ss[0], r_su[0], 0.0f);
}

// ---------------- Kernel C: finalize ----------------
__global__ void finalize_kernel(float* __restrict__ out, int nb)
{
    __shared__ float r_se[128], r_ss[128], r_su[128];
    const int t = threadIdx.x;
    float se = 0.0f, ss = 0.0f, su = 0.0f;
    for (int i = t; i < nb; i += 128) {
        float4 p = g_part[i];
        se += p.x; ss += p.y; su += p.z;
    }
    r_se[t] = se; r_ss[t] = ss; r_su[t] = su;
    __syncthreads();
    for (int off = 64; off > 0; off >>= 1) {
        if (t < off) {
            r_se[t] += r_se[t + off];
            r_ss[t] += r_ss[t + off];
            r_su[t] += r_su[t + off];
        }
        __syncthreads();
    }
    if (t == 0) out[0] = r_su[0] - r_ss[0] / r_se[0];
}

// ---------------- launch ----------------
extern "C" void kernel_launch(void* const* d_in, const int* in_sizes, int n_in,
                              void* d_out, int out_size)
{
    const int*   lca    = (const int*)  d_in[0];
    const int*   l_idx  = (const int*)  d_in[1];
    const int*   r_idx  = (const int*)  d_in[2];
    const float* sims   = (const float*)d_in[3];
    const float* emb    = (const float*)d_in[4];
    const float* leaves = (const float*)d_in[5];
    const float* scale  = (const float*)d_in[6];

    const int n_pairs  = in_sizes[1];
    const int n_leaves = in_sizes[5] / 128;

    const int smemA = 2 * STAGE_BYTES;                      // 135168
    const int smemB = (n_leaves * 2 + 127) & ~127;          // bulk-chunk rounded
    cudaFuncSetAttribute(leaf_dist_kernel,
                         cudaFuncAttributeMaxDynamicSharedMemorySize, smemA);
    cudaFuncSetAttribute(pair_reduce_kernel,
                         cudaFuncAttributeMaxDynamicSharedMemorySize,
                         (N_LEAVES_MAX * 2 + 127) & ~127);

    int sm_count = 0;
    cudaDeviceGetAttribute(&sm_count, cudaDevAttrMultiProcessorCount, 0);
    if (sm_count <= 0 || sm_count > MAXB) sm_count = 148;

    leaf_dist_kernel<<<sm_count, 128, smemA>>>(lca, emb, leaves, scale, n_leaves);
    pair_reduce_kernel<<<GRID_B, 1024, smemB>>>(l_idx, r_idx, sims, n_pairs, n_leaves);
    finalize_kernel<<<1, 128>>>((float*)d_out, GRID_B);
}

// round 6
// speedup vs baseline: 1.1825x; 1.1825x over previous
#include <cuda_runtime.h>
#include <cuda_fp16.h>
#include <cstdint>
#include <math.h>

// ---------------- scratch (no allocations allowed) ----------------
#define N_LEAVES_MAX 100000
#define MAXB 256
#define GRID_B 64

__device__ __align__(16) __half g_dleaf[N_LEAVES_MAX + 128];
__device__ int    g_maxint;          // max d as ordered int (positive floats)
__device__ float4 g_part[MAXB];      // (sum_exp, sum_sims_exp, sum_sims, -)

// ---------------- mbarrier / bulk-copy helpers ----------------
__device__ __forceinline__ void mbar_init(unsigned int mbar, unsigned int cnt) {
    asm volatile("mbarrier.init.shared.b64 [%0], %1;" :: "r"(mbar), "r"(cnt) : "memory");
}
__device__ __forceinline__ void mbar_expect_tx(unsigned int mbar, unsigned int bytes) {
    asm volatile("mbarrier.arrive.expect_tx.shared.b64 _, [%0], %1;"
                 :: "r"(mbar), "r"(bytes) : "memory");
}
__device__ __forceinline__ void mbar_wait(unsigned int mbar, unsigned int phase) {
    asm volatile(
        "{\n\t"
        ".reg .pred P1;\n\t"
        "WAIT_LOOP_%=:\n\t"
        "mbarrier.try_wait.parity.acquire.cta.shared::cta.b64 P1, [%0], %1, 0x989680;\n\t"
        "@P1 bra.uni WAIT_DONE_%=;\n\t"
        "bra.uni WAIT_LOOP_%=;\n\t"
        "WAIT_DONE_%=:\n\t"
        "}"
        :: "r"(mbar), "r"(phase) : "memory");
}
__device__ __forceinline__ void bulk_g2s(unsigned int dst, const void* src,
                                         unsigned int bytes, unsigned int mbar) {
    asm volatile(
        "cp.async.bulk.shared::cluster.global.mbarrier::complete_tx::bytes [%0], [%1], %2, [%3];"
        :: "r"(dst), "l"(src), "r"(bytes), "r"(mbar) : "memory");
}

#define TILE_A 128
#define STAGE_BYTES (TILE_A * 512)           // 65536, unpadded rows

// ---------------- Kernel A: persistent double-buffered leaf distances ----------------
// One 64KB bulk copy per tile; rotated smem reads (conflict-free without padding).
__global__ __launch_bounds__(128) void leaf_dist_kernel(
        const int* __restrict__ lca,
        const float* __restrict__ emb,
        const float* __restrict__ leaves,
        const float* __restrict__ scale,
        int n_leaves)
{
    extern __shared__ __align__(16) float sm[];   // [2][TILE_A*128]
    __shared__ __align__(16) float s_e[128];
    __shared__ float s_red[128];
    __shared__ float s_nx, s_inv;
    __shared__ __align__(8) unsigned long long s_mbar[2];

    const int t       = threadIdx.x;
    const int bx      = blockIdx.x;
    const int grid    = gridDim.x;
    const int n_tiles = (n_leaves + TILE_A - 1) / TILE_A;
    const unsigned int sbase = (unsigned int)__cvta_generic_to_shared(sm);
    const unsigned int mb0   = (unsigned int)__cvta_generic_to_shared(&s_mbar[0]);

    const int my_n = (bx < n_tiles) ? (n_tiles - bx + grid - 1) / grid : 0;

    if (t == 0) { mbar_init(mb0, 1); mbar_init(mb0 + 8, 1); }
    __syncthreads();

    // ---- prologue: expect + single bulk copy for stages 0,1 ----
    if (t == 0) {
        #pragma unroll
        for (int p = 0; p < 2; p++) {
            int tile = bx + p * grid;
            if (tile < n_tiles) {
                int leaf0 = tile * TILE_A;
                unsigned int bytes = (unsigned int)min(TILE_A, n_leaves - leaf0) * 512u;
                mbar_expect_tx(mb0 + p * 8, bytes);
                bulk_g2s(sbase + p * STAGE_BYTES,
                         leaves + (size_t)leaf0 * 128, bytes, mb0 + p * 8);
            }
        }
    }

    // ---- build e1 while prologue loads fly ----
    const float* erow = emb + (long long)lca[0] * 128;
    float w = erow[t];
    s_red[t] = w * w;
    __syncthreads();
    for (int off = 64; off > 0; off >>= 1) {
        if (t < off) s_red[t] += s_red[t + off];
        __syncthreads();
    }
    if (t == 0) {
        float norm2  = s_red[0];
        float s      = fminf(fmaxf(scale[0], 0.01f), 1.0f - 0.001f);
        float factor = s / fmaxf(sqrtf(norm2), 1e-12f);
        float nx     = factor * factor * norm2;
        s_nx  = nx;
        s_inv = 1.0f / (1.0f - nx);
        s_red[0] = factor;
    }
    __syncthreads();
    s_e[t] = w * s_red[0];
    __syncthreads();                      // s_e/s_nx/s_inv visible

    float dmax = 0.0f;
    const float4* er = reinterpret_cast<const float4*>(s_e);

    #pragma unroll 1
    for (int i = 0; i < my_n; i++) {
        const int st = i & 1;
        mbar_wait(mb0 + st * 8, (i >> 1) & 1);

        const int tile  = bx + i * grid;
        const int leaf0 = tile * TILE_A;
        const int valid = min(TILE_A, n_leaves - leaf0);

        if (t < valid) {
            // row t of stage st; rotated read order (k' = (k+t)&31) keeps all
            // 32 banks evenly loaded every phase despite unpadded 512B rows.
            const float4* yr = reinterpret_cast<const float4*>(sm) +
                               (size_t)st * (STAGE_BYTES / 16) + t * 32;
            float dot = 0.0f, ny = 0.0f;
            #pragma unroll
            for (int k = 0; k < 32; k++) {
                int kk = (k + t) & 31;
                float4 y = yr[kk];
                float4 e = er[kk];
                dot = fmaf(e.x, y.x, fmaf(e.y, y.y, fmaf(e.z, y.z, fmaf(e.w, y.w, dot))));
                ny  = fmaf(y.x, y.x, fmaf(y.y, y.y, fmaf(y.z, y.z, fmaf(y.w, y.w, ny))));
            }
            float sq  = s_nx - 2.0f * dot + ny;
            float arg = 1.0f + 2.0f * sq * s_inv / (1.0f - ny);
            arg = fmaxf(arg, 1.0f + 1e-7f);
            float d = acoshf(arg);
            g_dleaf[leaf0 + t] = __float2half(d);
            dmax = fmaxf(dmax, d);
        }

        // ---- refill this stage with tile i+2 (single bulk op) ----
        const int tile2 = bx + (i + 2) * grid;
        __syncthreads();   // stage fully consumed by all threads
        if (t == 0 && tile2 < n_tiles) {
            int l2 = tile2 * TILE_A;
            unsigned int bytes = (unsigned int)min(TILE_A, n_leaves - l2) * 512u;
            mbar_expect_tx(mb0 + st * 8, bytes);
            bulk_g2s(sbase + st * STAGE_BYTES,
                     leaves + (size_t)l2 * 128, bytes, mb0 + st * 8);
        }
    }

    // ---- block max -> global atomicMax (deterministic) ----
    s_red[t] = dmax;
    __syncthreads();
    for (int off = 64; off > 0; off >>= 1) {
        if (t < off) s_red[t] = fmaxf(s_red[t], s_red[t + off]);
        __syncthreads();
    }
    if (t == 0) atomicMax(&g_maxint, __float_as_int(s_red[0]));
}

// ---------------- Kernel B: branchless softmax partial sums ----------------
__global__ __launch_bounds__(1024) void pair_reduce_kernel(
        const int* __restrict__ l_idx,
        const int* __restrict__ r_idx,
        const float* __restrict__ sims,
        int n_pairs, int n_leaves)
{
    extern __shared__ __half s_tab[];
    __shared__ float r_se[1024], r_ss[1024], r_su[1024];
    __shared__ __align__(8) unsigned long long s_mbar;

    const int t = threadIdx.x;
    const unsigned int sb  = (unsigned int)__cvta_generic_to_shared(s_tab);
    const unsigned int mbr = (unsigned int)__cvta_generic_to_shared(&s_mbar);

    const unsigned int totr  = ((unsigned int)n_leaves * 2u + 127u) & ~127u;
    const unsigned int chunk = totr / 8u;

    if (t == 0) { mbar_init(mbr, 1); mbar_expect_tx(mbr, totr); }
    __syncthreads();
    if (t < 8)
        bulk_g2s(sb + t * chunk, reinterpret_cast<const char*>(g_dleaf) + t * chunk,
                 chunk, mbr);

    const float M = 40.0f * __int_as_float(g_maxint);

    mbar_wait(mbr, 0);

    float se = 0.0f, ss = 0.0f, su = 0.0f;

    const int n4 = n_pairs >> 2;
    const int4*   l4 = reinterpret_cast<const int4*>(l_idx);
    const int4*   r4 = reinterpret_cast<const int4*>(r_idx);
    const float4* s4 = reinterpret_cast<const float4*>(sims);
    const int stride = gridDim.x * blockDim.x;

    #pragma unroll 2
    for (int i = blockIdx.x * blockDim.x + t; i < n4; i += stride) {
        int4   li = l4[i];
        int4   ri = r4[i];
        float4 si = s4[i];
        float e0 = __expf(fmaf(20.0f, __half2float(s_tab[li.x]) + __half2float(s_tab[ri.x]), -M));
        float e1 = __expf(fmaf(20.0f, __half2float(s_tab[li.y]) + __half2float(s_tab[ri.y]), -M));
        float e2 = __expf(fmaf(20.0f, __half2float(s_tab[li.z]) + __half2float(s_tab[ri.z]), -M));
        float e3 = __expf(fmaf(20.0f, __half2float(s_tab[li.w]) + __half2float(s_tab[ri.w]), -M));
        se += (e0 + e1) + (e2 + e3);
        ss  = fmaf(si.x, e0, fmaf(si.y, e1, fmaf(si.z, e2, fmaf(si.w, e3, ss))));
        su += (si.x + si.y) + (si.z + si.w);
    }
    // scalar tail
    if (blockIdx.x == 0) {
        for (int i = n4 * 4 + t; i < n_pairs; i += blockDim.x) {
            float e = __expf(fmaf(20.0f,
                        __half2float(s_tab[l_idx[i]]) + __half2float(s_tab[r_idx[i]]), -M));
            float si = sims[i];
            se += e; ss = fmaf(si, e, ss); su += si;
        }
    }

    r_se[t] = se; r_ss[t] = ss; r_su[t] = su;
    __syncthreads();
    for (int off = 512; off > 0; off >>= 1) {
        if (t < off) {
            r_se[t] += r_se[t + off];
            r_ss[t] += r_ss[t + off];
            r_su[t] += r_su[t + off];
        }
        __syncthreads();
    }
    if (t == 0) g_part[blockIdx.x] = make_float4(r_se[0], r_ss[0], r_su[0], 0.0f);
}

// ---------------- Kernel C: finalize ----------------
__global__ void finalize_kernel(float* __restrict__ out, int nb)
{
    __shared__ float r_se[128], r_ss[128], r_su[128];
    const int t = threadIdx.x;
    float se = 0.0f, ss = 0.0f, su = 0.0f;
    for (int i = t; i < nb; i += 128) {
        float4 p = g_part[i];
        se += p.x; ss += p.y; su += p.z;
    }
    r_se[t] = se; r_ss[t] = ss; r_su[t] = su;
    __syncthreads();
    for (int off = 64; off > 0; off >>= 1) {
        if (t < off) {
            r_se[t] += r_se[t + off];
            r_ss[t] += r_ss[t + off];
            r_su[t] += r_su[t + off];
        }
        __syncthreads();
    }
    if (t == 0) out[0] = r_su[0] - r_ss[0] / r_se[0];
}

// ---------------- launch ----------------
extern "C" void kernel_launch(void* const* d_in, const int* in_sizes, int n_in,
                              void* d_out, int out_size)
{
    const int*   lca    = (const int*)  d_in[0];
    const int*   l_idx  = (const int*)  d_in[1];
    const int*   r_idx  = (const int*)  d_in[2];
    const float* sims   = (const float*)d_in[3];
    const float* emb    = (const float*)d_in[4];
    const float* leaves = (const float*)d_in[5];
    const float* scale  = (const float*)d_in[6];

    const int n_pairs  = in_sizes[1];
    const int n_leaves = in_sizes[5] / 128;

    const int smemA = 2 * STAGE_BYTES;                      // 131072
    const int smemB = (n_leaves * 2 + 127) & ~127;
    cudaFuncSetAttribute(leaf_dist_kernel,
                         cudaFuncAttributeMaxDynamicSharedMemorySize, smemA);
    cudaFuncSetAttribute(pair_reduce_kernel,
                         cudaFuncAttributeMaxDynamicSharedMemorySize,
                         (N_LEAVES_MAX * 2 + 127) & ~127);

    int sm_count = 0;
    cudaDeviceGetAttribute(&sm_count, cudaDevAttrMultiProcessorCount, 0);
    if (sm_count <= 0 || sm_count > MAXB) sm_count = 148;

    leaf_dist_kernel<<<sm_count, 128, smemA>>>(lca, emb, leaves, scale, n_leaves);
    pair_reduce_kernel<<<GRID_B, 1024, smemB>>>(l_idx, r_idx, sims, n_pairs, n_leaves);
    finalize_kernel<<<1, 128>>>((float*)d_out, GRID_B);
}